// round 15
// baseline (speedup 1.0000x reference)
#include <cuda_runtime.h>
#include <cuda_fp16.h>
#include <math.h>
#include <stdint.h>

#define DDIM 256
#define PDIM 64
#define MTILE 128
#define NTHREADS 256

#define KQP 144   // split buffers [rows][64k] fp16 + 16B pad
#define SP  272   // sims [128 m][64 p] f32 + pad
#define WP  144   // W fp16 [128 m][64 p] + pad

// ---- smem offsets (bytes) ----
#define QH_O 0            // Q hi quarter [128][144]  = 18432
#define QL_O 18432        // Q lo quarter             = 18432
#define CH_O 36864        // C hi quarter [64][144]   = 9216
#define CL_O 46080        // C lo quarter             = 9216
#define S_O  0            // sims [128][272] = 34816  (alias QH/QL, dead after GEMM1)
#define WH_O 36864        // W fp16 [128][144] = 18432 (alias CH/CL, dead after GEMM1)
#define C2_O 55296        // GEMM2 C buffers: 2 x 9216 = 55296..73728
#define C2STRIDE 9216
#define QSS_O 73728       // 128 f32
#define CISM_O 74240      // 64 f32
#define NEGM_O 74496      // 64 f32
#define SMEM_BYTES 74752  // x3 = 224256 <= 233472

__device__ __align__(16) unsigned short gCH[PDIM * DDIM];
__device__ __align__(16) unsigned short gCL[PDIM * DDIM];
__device__ float gCISM[PDIM];
__device__ float gNEGM[PDIM];

__device__ __forceinline__ uint32_t smem_u32(const void* p) {
    uint32_t a;
    asm("{ .reg .u64 t; cvta.to.shared.u64 t, %1; cvt.u32.u64 %0, t; }" : "=r"(a) : "l"(p));
    return a;
}
#define CPA16(dst, src) \
    asm volatile("cp.async.cg.shared.global [%0], [%1], 16;" :: "r"(dst), "l"(src) : "memory")
#define CPA_COMMIT() asm volatile("cp.async.commit_group;" ::: "memory")
#define CPA_WAIT0()  asm volatile("cp.async.wait_group 0;" ::: "memory")
#define CPA_WAIT1()  asm volatile("cp.async.wait_group 1;" ::: "memory")

__device__ __forceinline__ void ldsm4(uint32_t addr, uint32_t& r0, uint32_t& r1,
                                      uint32_t& r2, uint32_t& r3) {
    asm volatile("ldmatrix.sync.aligned.m8n8.x4.shared.b16 {%0,%1,%2,%3}, [%4];"
                 : "=r"(r0), "=r"(r1), "=r"(r2), "=r"(r3) : "r"(addr));
}
__device__ __forceinline__ void ldsm4t(uint32_t addr, uint32_t& r0, uint32_t& r1,
                                       uint32_t& r2, uint32_t& r3) {
    asm volatile("ldmatrix.sync.aligned.m8n8.x4.trans.shared.b16 {%0,%1,%2,%3}, [%4];"
                 : "=r"(r0), "=r"(r1), "=r"(r2), "=r"(r3) : "r"(addr));
}
__device__ __forceinline__ void mma16816(float* d, uint32_t a0, uint32_t a1, uint32_t a2,
                                         uint32_t a3, uint32_t b0, uint32_t b1) {
    asm volatile("mma.sync.aligned.m16n8k16.row.col.f32.f16.f16.f32 "
                 "{%0,%1,%2,%3}, {%4,%5,%6,%7}, {%8,%9}, {%0,%1,%2,%3};"
                 : "+f"(d[0]), "+f"(d[1]), "+f"(d[2]), "+f"(d[3])
                 : "r"(a0), "r"(a1), "r"(a2), "r"(a3), "r"(b0), "r"(b1));
}
// 8 MMAs: 32 rows (a0..a7) x 32 cols (e = cols 0-15, f = cols 16-31)
#define MMA8(acc, a0,a1,a2,a3,a4,a5,a6,a7, e0,e1,e2,e3, f0,f1,f2,f3) do { \
    mma16816((acc)[0], a0,a1,a2,a3, e0,e2); \
    mma16816((acc)[1], a0,a1,a2,a3, e1,e3); \
    mma16816((acc)[2], a0,a1,a2,a3, f0,f2); \
    mma16816((acc)[3], a0,a1,a2,a3, f1,f3); \
    mma16816((acc)[4], a4,a5,a6,a7, e0,e2); \
    mma16816((acc)[5], a4,a5,a6,a7, e1,e3); \
    mma16816((acc)[6], a4,a5,a6,a7, f0,f2); \
    mma16816((acc)[7], a4,a5,a6,a7, f1,f3); \
} while (0)

// packed f16x2 convert (cvt.rn, same as __float2half): x1 -> hi, x0 -> lo
__device__ __forceinline__ uint32_t cvt2h(float x1, float x0) {
    uint32_t r;
    asm("cvt.rn.f16x2.f32 %0, %1, %2;" : "=r"(r) : "f"(x1), "f"(x0));
    return r;
}
__device__ __forceinline__ float2 h2f2(uint32_t p) {
    __half2 h = *reinterpret_cast<__half2*>(&p);
    return __half22float2(h);
}

// 8 fp32 -> fp16 hi/lo splits (16B each); accumulate sumsq
__device__ __forceinline__ void conv8h(const float4* src, char* dh, char* dl,
                                       uint32_t off, float& acc) {
    float4 a = src[0], b = src[1];
    float xs[8] = {a.x, a.y, a.z, a.w, b.x, b.y, b.z, b.w};
    uint32_t H[4], L[4];
    #pragma unroll
    for (int i = 0; i < 4; ++i) {
        float x0 = xs[2 * i], x1 = xs[2 * i + 1];
        acc = fmaf(x0, x0, acc);
        acc = fmaf(x1, x1, acc);
        uint32_t h = cvt2h(x1, x0);
        float2 hf = h2f2(h);
        H[i] = h;
        L[i] = cvt2h(x1 - hf.y, x0 - hf.x);
    }
    *(uint4*)(dh + off) = make_uint4(H[0], H[1], H[2], H[3]);
    *(uint4*)(dl + off) = make_uint4(L[0], L[1], L[2], L[3]);
}

// ================= prep kernel: fp16-split C once, norms + mask =================
__global__ void centroid_prep(const float* __restrict__ gc, const int* __restrict__ gmask) {
    const int wid = threadIdx.x >> 5, lane = threadIdx.x & 31;
    const int row = blockIdx.x * 8 + wid;
    const float4* src = (const float4*)(gc + (size_t)row * DDIM) + lane * 2;
    float4 a = src[0], b = src[1];
    float xs[8] = {a.x, a.y, a.z, a.w, b.x, b.y, b.z, b.w};
    float acc = 0.f;
    uint32_t H[4], L[4];
    #pragma unroll
    for (int i = 0; i < 4; ++i) {
        float x0 = xs[2 * i], x1 = xs[2 * i + 1];
        acc = fmaf(x0, x0, acc);
        acc = fmaf(x1, x1, acc);
        uint32_t h = cvt2h(x1, x0);
        float2 hf = h2f2(h);
        H[i] = h;
        L[i] = cvt2h(x1 - hf.y, x0 - hf.x);
    }
    const int idx = row * DDIM + lane * 8;
    *(uint4*)(gCH + idx) = make_uint4(H[0], H[1], H[2], H[3]);
    *(uint4*)(gCL + idx) = make_uint4(L[0], L[1], L[2], L[3]);
    #pragma unroll
    for (int off = 1; off < 32; off <<= 1)
        acc += __shfl_xor_sync(0xffffffffu, acc, off);
    if (lane == 0) {
        int mk = gmask[row];
        gCISM[row] = mk ? rsqrtf(fmaxf(acc, 1e-24f)) : 0.f;
        gNEGM[row] = mk ? 0.f : -1e9f;
    }
}

// cp.async one quarter (128B/row) of a precomputed split into pitched smem
__device__ __forceinline__ void copy_cq(uint32_t dstbase, const unsigned short* gsrc,
                                        int row, int seg, int kq) {
    uint32_t dst = dstbase + (uint32_t)(row * KQP + seg * 32);
    uint64_t src = __cvta_generic_to_global(gsrc + row * DDIM + kq * 64 + seg * 16);
    CPA16(dst, src);
    CPA16(dst + 16, src + 16);
}

__global__ void __launch_bounds__(NTHREADS, 3)
centroid_main(const float* __restrict__ gq,
              float* __restrict__ gctx,
              float* __restrict__ gw,
              float* __restrict__ ghard)
{
    extern __shared__ char sm[];
    const uint32_t smb = smem_u32(sm);
    const int t = threadIdx.x;
    const int wid = t >> 5, lane = t & 31;
    const int mbase = blockIdx.x * MTILE;

    float* qssf = (float*)(sm + QSS_O);
    float* cism = (float*)(sm + CISM_O);
    float* negm = (float*)(sm + NEGM_O);

    // GEMM1 warp mapping: 4M x 2N grid of 32x32 tiles, 3 split passes each
    const int mrow = (wid & 3) * 32;
    const int ncol = (wid >> 2) * 32;
    const int row4 = t >> 2, seg4 = t & 3;      // C copies: 4 thr/row
    const int row2 = t >> 1, seg2 = t & 1;      // Q convert: 2 thr/row, 32 elems each

    if (t < 64) {
        cism[t] = gCISM[t];
        negm[t] = gNEGM[t];
    }

    float qacc = 0.f;
    float acc[8][4];
    #pragma unroll
    for (int i = 0; i < 8; ++i)
        #pragma unroll
        for (int j = 0; j < 4; ++j) acc[i][j] = 0.f;

    const uint32_t lrow = (uint32_t)(lane & 15);
    const uint32_t lk = (uint32_t)((lane >> 4) * 16);
    const uint32_t aQH = smb + QH_O + (mrow + lrow) * KQP + lk;
    const uint32_t aQL = smb + QL_O + (mrow + lrow) * KQP + lk;
    const uint32_t bCH = smb + CH_O + (ncol + lrow) * KQP + lk;
    const uint32_t bCL = smb + CL_O + (ncol + lrow) * KQP + lk;

    // ================= GEMM1 over four K-quarters, 3 fp16 split passes =================
    #pragma unroll 1
    for (int kq = 0; kq < 4; ++kq) {
        copy_cq(smb + CH_O, gCH, row4, seg4, kq);
        copy_cq(smb + CL_O, gCL, row4, seg4, kq);
        CPA_COMMIT();
        {
            const float4* src = (const float4*)(gq + (size_t)(mbase + row2) * DDIM + kq * 64 + seg2 * 32);
            uint32_t base = (uint32_t)(row2 * KQP + seg2 * 64);
            conv8h(src,     sm + QH_O, sm + QL_O, base,      qacc);
            conv8h(src + 2, sm + QH_O, sm + QL_O, base + 16, qacc);
            conv8h(src + 4, sm + QH_O, sm + QL_O, base + 32, qacc);
            conv8h(src + 6, sm + QH_O, sm + QL_O, base + 48, qacc);
        }
        if (kq == 3) {
            qacc += __shfl_xor_sync(0xffffffffu, qacc, 1);
            if (seg2 == 0) qssf[row2] = qacc;
        }
        CPA_WAIT0();
        __syncthreads();

        #pragma unroll
        for (int ks = 0; ks < 4; ++ks) {
            uint32_t a0, a1, a2, a3, a4, a5, a6, a7;
            uint32_t e0, e1, e2, e3, f0, f1, f2, f3;   // CH frags, held
            uint32_t u0, u1, u2, u3, v0, v1, v2, v3;   // CL frags
            ldsm4(aQH + ks * 32, a0, a1, a2, a3);
            ldsm4(aQH + 16 * KQP + ks * 32, a4, a5, a6, a7);
            ldsm4(bCH + ks * 32, e0, e1, e2, e3);
            ldsm4(bCH + 16 * KQP + ks * 32, f0, f1, f2, f3);
            MMA8(acc, a0,a1,a2,a3,a4,a5,a6,a7, e0,e1,e2,e3, f0,f1,f2,f3);   // QH x CH
            ldsm4(bCL + ks * 32, u0, u1, u2, u3);
            ldsm4(bCL + 16 * KQP + ks * 32, v0, v1, v2, v3);
            MMA8(acc, a0,a1,a2,a3,a4,a5,a6,a7, u0,u1,u2,u3, v0,v1,v2,v3);   // QH x CL
            ldsm4(aQL + ks * 32, a0, a1, a2, a3);
            ldsm4(aQL + 16 * KQP + ks * 32, a4, a5, a6, a7);
            MMA8(acc, a0,a1,a2,a3,a4,a5,a6,a7, e0,e1,e2,e3, f0,f1,f2,f3);   // QL x CH
        }
        __syncthreads();
    }

    // ---- store sims (32x32 tile per warp; aliases dead Q region) ----
    {
        const int r0 = mrow + (lane >> 2);
        const int cb = ncol + (lane & 3) * 2;
        #pragma unroll
        for (int mf = 0; mf < 2; ++mf)
            #pragma unroll
            for (int nf = 0; nf < 4; ++nf) {
                float* a = acc[mf * 4 + nf];
                *(float2*)(sm + S_O + (r0 + mf * 16) * SP + (cb + nf * 8) * 4) = make_float2(a[0], a[1]);
                *(float2*)(sm + S_O + (r0 + mf * 16 + 8) * SP + (cb + nf * 8) * 4) = make_float2(a[2], a[3]);
            }
    }
    __syncthreads();

    // ---- prefetch GEMM2 d-quarter 0 (CH only) into buffer 0 ----
    copy_cq(smb + C2_O, gCH, row4, seg4, 0);
    CPA_COMMIT();

    // ================= softmax + argmax: 2 threads per row =================
    {
        const int m = t >> 1, part = t & 1;
        const float qr = rsqrtf(fmaxf(qssf[m], 1e-24f));
        const float4* s0 = (const float4*)(sm + S_O + m * SP) + part * 8;
        float s[32];
        float mx = -INFINITY;
        int mi = PDIM;
        #pragma unroll
        for (int gg = 0; gg < 8; ++gg) {
            float4 v = s0[gg];
            float vv[4] = {v.x, v.y, v.z, v.w};
            #pragma unroll
            for (int i = 0; i < 4; ++i) {
                int p = part * 32 + gg * 4 + i;
                float val = fmaf(vv[i] * qr, cism[p], negm[p]);
                s[gg * 4 + i] = val;
                if (val > mx) { mx = val; mi = p; }     // strict >: first index wins
            }
        }
        {
            float omx = __shfl_xor_sync(0xffffffffu, mx, 1);
            int   omi = __shfl_xor_sync(0xffffffffu, mi, 1);
            if (omx > mx || (omx == mx && omi < mi)) { mx = omx; mi = omi; }
        }
        float ssum = 0.f;
        #pragma unroll
        for (int i = 0; i < 32; ++i) {
            float e = expf(s[i] - mx);
            s[i] = e;
            ssum += e;
        }
        ssum += __shfl_xor_sync(0xffffffffu, ssum, 1);
        const float inv = 1.0f / ssum;

        float4* gwp = (float4*)(gw + (size_t)(mbase + m) * PDIM + part * 32);
        char* wh = sm + WH_O + m * WP + part * 64;
        #pragma unroll
        for (int gg = 0; gg < 4; ++gg) {
            float w0 = s[8 * gg + 0] * inv, w1 = s[8 * gg + 1] * inv;
            float w2 = s[8 * gg + 2] * inv, w3 = s[8 * gg + 3] * inv;
            float w4 = s[8 * gg + 4] * inv, w5 = s[8 * gg + 5] * inv;
            float w6 = s[8 * gg + 6] * inv, w7 = s[8 * gg + 7] * inv;
            gwp[2 * gg]     = make_float4(w0, w1, w2, w3);
            gwp[2 * gg + 1] = make_float4(w4, w5, w6, w7);
            uint32_t h0 = cvt2h(w1, w0), h1 = cvt2h(w3, w2);
            uint32_t h2 = cvt2h(w5, w4), h3 = cvt2h(w7, w6);
            *(uint4*)(wh + gg * 16) = make_uint4(h0, h1, h2, h3);
        }
        if (part == 0) ghard[mbase + m] = (float)mi;
    }
    __syncthreads();

    // ================= GEMM2: 4 d-quarter rounds, double-buffered, single fp16 pass =================
    {
        const int mrow2 = (wid & 3) * 32;
        const int dtile = (wid >> 2) * 32;
        const uint32_t btrow = (uint32_t)((lane >> 4) * 8 + (lane & 7));
        const uint32_t btcol = (uint32_t)(((lane >> 3) & 1) * 16);
        const uint32_t aWHr = smb + WH_O + (mrow2 + lrow) * WP + lk;

        #pragma unroll 1
        for (int dq = 0; dq < 4; ++dq) {
            const uint32_t cbuf = C2_O + (uint32_t)(dq & 1) * C2STRIDE;
            if (dq < 3) {
                const uint32_t nbuf = C2_O + (uint32_t)((dq + 1) & 1) * C2STRIDE;
                copy_cq(smb + nbuf, gCH, row4, seg4, dq + 1);
                CPA_COMMIT();
                CPA_WAIT1();
            } else {
                CPA_WAIT0();
            }
            __syncthreads();

            float dd[8][4];
            #pragma unroll
            for (int i = 0; i < 8; ++i)
                #pragma unroll
                for (int j = 0; j < 4; ++j) dd[i][j] = 0.f;

            const uint32_t bC2 = smb + cbuf + btrow * KQP + dtile * 2 + btcol;
            #pragma unroll
            for (int ks = 0; ks < 4; ++ks) {
                uint32_t a0, a1, a2, a3, a4, a5, a6, a7;
                uint32_t r0, r1, r2, r3, s0, s1, s2, s3;
                ldsm4(aWHr + ks * 32, a0, a1, a2, a3);
                ldsm4(aWHr + 16 * WP + ks * 32, a4, a5, a6, a7);
                ldsm4t(bC2 + ks * 16 * KQP, r0, r1, r2, r3);         // d 0..15
                ldsm4t(bC2 + ks * 16 * KQP + 32, s0, s1, s2, s3);    // d 16..31
                mma16816(dd[0], a0, a1, a2, a3, r0, r2);
                mma16816(dd[1], a0, a1, a2, a3, r1, r3);
                mma16816(dd[2], a0, a1, a2, a3, s0, s2);
                mma16816(dd[3], a0, a1, a2, a3, s1, s3);
                mma16816(dd[4], a4, a5, a6, a7, r0, r2);
                mma16816(dd[5], a4, a5, a6, a7, r1, r3);
                mma16816(dd[6], a4, a5, a6, a7, s0, s2);
                mma16816(dd[7], a4, a5, a6, a7, s1, s3);
            }
            const int r0l = lane >> 2;
            const int cb = dq * 64 + dtile + (lane & 3) * 2;
            #pragma unroll
            for (int mf = 0; mf < 2; ++mf) {
                float* gr0 = gctx + (size_t)(mbase + mrow2 + mf * 16 + r0l) * DDIM;
                float* gr1 = gr0 + 8 * DDIM;
                #pragma unroll
                for (int nf = 0; nf < 4; ++nf) {
                    float* a = dd[mf * 4 + nf];
                    *(float2*)(gr0 + cb + nf * 8) = make_float2(a[0], a[1]);
                    *(float2*)(gr1 + cb + nf * 8) = make_float2(a[2], a[3]);
                }
            }
            __syncthreads();
        }
    }
}

extern "C" void kernel_launch(void* const* d_in, const int* in_sizes, int n_in,
                              void* d_out, int out_size)
{
    const float* q = (const float*)d_in[0];
    const float* c = (const float*)d_in[1];
    const int*   mask = (const int*)d_in[2];

    const int Pn = in_sizes[2];              // 64
    const int Dn = in_sizes[1] / Pn;         // 256
    const int B  = in_sizes[0] / Dn;         // 131072

    float* out  = (float*)d_out;
    float* ctx  = out;                           // [B, D]
    float* w    = out + (size_t)B * Dn;          // [B, P]
    float* hard = w + (size_t)B * Pn;            // [B]

    centroid_prep<<<8, 256>>>(c, mask);
    cudaFuncSetAttribute(centroid_main,
                         cudaFuncAttributeMaxDynamicSharedMemorySize, SMEM_BYTES);
    centroid_main<<<B / MTILE, NTHREADS, SMEM_BYTES>>>(q, ctx, w, hard);
}